// round 1
// baseline (speedup 1.0000x reference)
#include <cuda_runtime.h>

#define CZ   128      // channel dim
#define HD   64       // H*D
#define NH   4        // heads
#define P    64       // pixels per CTA
#define NT   256      // threads per CTA
#define XST  132      // padded stride for 128-wide LN'd rows (conflict-free column reads)
#define QST  68       // padded stride for 64-wide Q/G/K/vals tiles

__device__ __forceinline__ float neg_inf() { return __int_as_float(0xff800000); }

__global__ void __launch_bounds__(NT, 1)
tpa_fused(const float* __restrict__ tmpl, const float* __restrict__ pair,
          const float* __restrict__ lpg, const float* __restrict__ lpb,
          const float* __restrict__ ltg, const float* __restrict__ ltb,
          const float* __restrict__ Wq,  const float* __restrict__ Wk,
          const float* __restrict__ Wv,  const float* __restrict__ Wg,
          const float* __restrict__ bg,  const float* __restrict__ Wo,
          const float* __restrict__ bo,  float* __restrict__ out,
          int R, int T)
{
    extern __shared__ float sm[];
    float* xs  = sm;                 // P x XST   : LN'd pair rows
    float* ts  = xs + P*XST;         // P x XST   : LN'd template rows (per t)
    float* wA  = ts + P*XST;         // 128x64    : Wq, then Wk, then Wo(64x128)
    float* wB  = wA + CZ*HD;         // 128x64    : Wg, then Wv
    float* qs  = wB + CZ*HD;         // P x QST   : Q
    float* gs  = qs + P*QST;         // P x QST   : G (sigmoid gate)
    float* ks  = gs + P*QST;         // P x QST   : K_t, later reused as vals
    float* r_s = ks + P*QST;         // P*NH      : online-softmax rescale
    float* w_s = r_s + P*NH;         // P*NH      : online-softmax weight
    float* l_s = w_s + P*NH;         // P*NH      : 1/denominator

    const int tid  = threadIdx.x;
    const int lane = tid & 31;
    const int wid  = tid >> 5;
    const long base = (long)blockIdx.x * P;

    // this lane owns columns c4..c4+3 of every 128-wide row it helps LN
    const int c4 = lane * 4;
    const float4 gp = *(const float4*)(lpg + c4);
    const float4 bp = *(const float4*)(lpb + c4);
    const float4 gt = *(const float4*)(ltg + c4);
    const float4 bt = *(const float4*)(ltb + c4);

    // ---------------- LN(pair) -> xs ----------------
    for (int r = wid; r < P; r += NT/32) {
        long row = base + r;
        float4 x = make_float4(0.f, 0.f, 0.f, 0.f);
        if (row < R) x = *(const float4*)(pair + row * CZ + c4);
        float s = x.x + x.y + x.z + x.w;
        float q = x.x*x.x + x.y*x.y + x.z*x.z + x.w*x.w;
        #pragma unroll
        for (int o = 16; o; o >>= 1) {
            s += __shfl_xor_sync(0xffffffffu, s, o);
            q += __shfl_xor_sync(0xffffffffu, q, o);
        }
        float m  = s * (1.f/CZ);
        float v  = fmaxf(q * (1.f/CZ) - m*m, 0.f);
        float ri = rsqrtf(v + 1e-5f);
        float* xr = xs + r * XST + c4;
        xr[0] = (x.x - m)*ri*gp.x + bp.x;
        xr[1] = (x.y - m)*ri*gp.y + bp.y;
        xr[2] = (x.z - m)*ri*gp.z + bp.z;
        xr[3] = (x.w - m)*ri*gp.w + bp.w;
    }
    // stage Wq, Wg
    for (int i = tid; i < CZ*HD/4; i += NT) {
        ((float4*)wA)[i] = ((const float4*)Wq)[i];
        ((float4*)wB)[i] = ((const float4*)Wg)[i];
    }
    __syncthreads();

    // ---------------- Q & G GEMMs: [64x128]@[128x64] ----------------
    const int cx = tid & 15;   // 16 groups of 4 columns
    const int py = tid >> 4;   // 16 groups of 4 pixels
    {
        float aq[4][4] = {};
        float ag[4][4] = {};
        #pragma unroll 4
        for (int k = 0; k < CZ; k++) {
            float4 wq = ((const float4*)(wA + k*HD))[cx];
            float4 wg = ((const float4*)(wB + k*HD))[cx];
            float xv[4];
            #pragma unroll
            for (int i = 0; i < 4; i++) xv[i] = xs[(py*4+i)*XST + k];
            #pragma unroll
            for (int i = 0; i < 4; i++) {
                aq[i][0] += xv[i]*wq.x; aq[i][1] += xv[i]*wq.y;
                aq[i][2] += xv[i]*wq.z; aq[i][3] += xv[i]*wq.w;
                ag[i][0] += xv[i]*wg.x; ag[i][1] += xv[i]*wg.y;
                ag[i][2] += xv[i]*wg.z; ag[i][3] += xv[i]*wg.w;
            }
        }
        float4 bg4 = ((const float4*)bg)[cx];
        #pragma unroll
        for (int i = 0; i < 4; i++) {
            float* qr = qs + (py*4+i)*QST + cx*4;
            float* gr = gs + (py*4+i)*QST + cx*4;
            qr[0] = aq[i][0]; qr[1] = aq[i][1]; qr[2] = aq[i][2]; qr[3] = aq[i][3];
            gr[0] = 1.f/(1.f + expf(-(ag[i][0] + bg4.x)));
            gr[1] = 1.f/(1.f + expf(-(ag[i][1] + bg4.y)));
            gr[2] = 1.f/(1.f + expf(-(ag[i][2] + bg4.z)));
            gr[3] = 1.f/(1.f + expf(-(ag[i][3] + bg4.w)));
        }
    }
    __syncthreads();

    // stage Wk, Wv (kept across the whole t loop)
    for (int i = tid; i < CZ*HD/4; i += NT) {
        ((float4*)wA)[i] = ((const float4*)Wk)[i];
        ((float4*)wB)[i] = ((const float4*)Wv)[i];
    }

    // online softmax state: thread tid owns (p = tid>>2, h = tid&3)
    float m_run = neg_inf();
    float l_run = 0.f;
    float accV[4][4] = {};           // thread (cx,py)'s vals accumulator

    for (int t = 0; t < T; t++) {
        // ---- LN(template_t) -> ts ----
        const float* tb = tmpl + (long)t * R * CZ;
        for (int r = wid; r < P; r += NT/32) {
            long row = base + r;
            float4 x = make_float4(0.f, 0.f, 0.f, 0.f);
            if (row < R) x = *(const float4*)(tb + row * CZ + c4);
            float s = x.x + x.y + x.z + x.w;
            float q = x.x*x.x + x.y*x.y + x.z*x.z + x.w*x.w;
            #pragma unroll
            for (int o = 16; o; o >>= 1) {
                s += __shfl_xor_sync(0xffffffffu, s, o);
                q += __shfl_xor_sync(0xffffffffu, q, o);
            }
            float m  = s * (1.f/CZ);
            float v  = fmaxf(q * (1.f/CZ) - m*m, 0.f);
            float ri = rsqrtf(v + 1e-5f);
            float* tr = ts + r * XST + c4;
            tr[0] = (x.x - m)*ri*gt.x + bt.x;
            tr[1] = (x.y - m)*ri*gt.y + bt.y;
            tr[2] = (x.z - m)*ri*gt.z + bt.z;
            tr[3] = (x.w - m)*ri*gt.w + bt.w;
        }
        __syncthreads();   // ts ready (also covers Wk/Wv staging on t==0)

        // ---- K GEMM -> ks ----
        {
            float ak[4][4] = {};
            #pragma unroll 4
            for (int k = 0; k < CZ; k++) {
                float4 wk = ((const float4*)(wA + k*HD))[cx];
                float tv[4];
                #pragma unroll
                for (int i = 0; i < 4; i++) tv[i] = ts[(py*4+i)*XST + k];
                #pragma unroll
                for (int i = 0; i < 4; i++) {
                    ak[i][0] += tv[i]*wk.x; ak[i][1] += tv[i]*wk.y;
                    ak[i][2] += tv[i]*wk.z; ak[i][3] += tv[i]*wk.w;
                }
            }
            #pragma unroll
            for (int i = 0; i < 4; i++) {
                float* kr = ks + (py*4+i)*QST + cx*4;
                kr[0] = ak[i][0]; kr[1] = ak[i][1]; kr[2] = ak[i][2]; kr[3] = ak[i][3];
            }
        }
        __syncthreads();

        // ---- scores + online softmax: one thread per (p,h) ----
        {
            const int p = tid >> 2, h = tid & 3;
            const float* qp = qs + p*QST + h*16;
            const float* kp = ks + p*QST + h*16;
            float sdot = 0.f;
            #pragma unroll
            for (int d = 0; d < 16; d++) sdot += qp[d]*kp[d];
            sdot *= 0.25f;  // 1/sqrt(D=16)
            float mn = fmaxf(m_run, sdot);
            float rr = expf(m_run - mn);   // exp(-inf)=0 on first template
            float ww = expf(sdot - mn);
            l_run = l_run * rr + ww;
            m_run = mn;
            r_s[tid] = rr;
            w_s[tid] = ww;
        }
        __syncthreads();

        // ---- V GEMM (registers) + online accumulate ----
        {
            float av[4][4] = {};
            #pragma unroll 4
            for (int k = 0; k < CZ; k++) {
                float4 wv = ((const float4*)(wB + k*HD))[cx];
                float tv[4];
                #pragma unroll
                for (int i = 0; i < 4; i++) tv[i] = ts[(py*4+i)*XST + k];
                #pragma unroll
                for (int i = 0; i < 4; i++) {
                    av[i][0] += tv[i]*wv.x; av[i][1] += tv[i]*wv.y;
                    av[i][2] += tv[i]*wv.z; av[i][3] += tv[i]*wv.w;
                }
            }
            const int h = cx >> 2;       // this thread's 4 cols live in one head
            #pragma unroll
            for (int i = 0; i < 4; i++) {
                float rr = r_s[(py*4+i)*NH + h];
                float ww = w_s[(py*4+i)*NH + h];
                #pragma unroll
                for (int j = 0; j < 4; j++)
                    accV[i][j] = accV[i][j]*rr + ww*av[i][j];
            }
        }
        __syncthreads();   // protect ts/ks before next t overwrites them
    }

    // ---- finalize softmax denominator ----
    l_s[tid] = 1.f / l_run;          // thread (p,h)
    __syncthreads();

    // ---- vals = accV * G / l  -> reuse ks as vals buffer ----
    {
        const int h = cx >> 2;
        #pragma unroll
        for (int i = 0; i < 4; i++) {
            float li = l_s[(py*4+i)*NH + h];
            float* vr = ks + (py*4+i)*QST + cx*4;
            const float* gr = gs + (py*4+i)*QST + cx*4;
            vr[0] = accV[i][0]*gr[0]*li;
            vr[1] = accV[i][1]*gr[1]*li;
            vr[2] = accV[i][2]*gr[2]*li;
            vr[3] = accV[i][3]*gr[3]*li;
        }
    }
    // stage Wo (64x128 = same 8192 floats) into wA
    for (int i = tid; i < HD*CZ/4; i += NT)
        ((float4*)wA)[i] = ((const float4*)Wo)[i];
    __syncthreads();

    // ---- out GEMM: [64x64]@[64x128] + bo ----
    {
        const int ox = tid & 31;   // 32 groups of 4 out-cols
        const int pz = tid >> 5;   // 8 groups of 8 pixels
        float ao[8][4] = {};
        #pragma unroll 4
        for (int k = 0; k < HD; k++) {
            float4 w4 = ((const float4*)(wA + k*CZ))[ox];
            #pragma unroll
            for (int i = 0; i < 8; i++) {
                float v = ks[(pz*8+i)*QST + k];
                ao[i][0] += v*w4.x; ao[i][1] += v*w4.y;
                ao[i][2] += v*w4.z; ao[i][3] += v*w4.w;
            }
        }
        float4 bo4 = ((const float4*)bo)[ox];
        #pragma unroll
        for (int i = 0; i < 8; i++) {
            long row = base + pz*8 + i;
            if (row < R) {
                float4 o;
                o.x = ao[i][0] + bo4.x;
                o.y = ao[i][1] + bo4.y;
                o.z = ao[i][2] + bo4.z;
                o.w = ao[i][3] + bo4.w;
                *(float4*)(out + row * CZ + ox*4) = o;
            }
        }
    }
}

extern "C" void kernel_launch(void* const* d_in, const int* in_sizes, int n_in,
                              void* d_out, int out_size)
{
    const float* tmpl = (const float*)d_in[0];
    const float* pair = (const float*)d_in[1];
    const float* lpg  = (const float*)d_in[2];
    const float* lpb  = (const float*)d_in[3];
    const float* ltg  = (const float*)d_in[4];
    const float* ltb  = (const float*)d_in[5];
    const float* Wq   = (const float*)d_in[6];
    const float* Wk   = (const float*)d_in[7];
    const float* Wv   = (const float*)d_in[8];
    const float* Wg   = (const float*)d_in[9];
    const float* bg   = (const float*)d_in[10];
    const float* Wo   = (const float*)d_in[11];
    const float* bo   = (const float*)d_in[12];
    float* out = (float*)d_out;

    const int R = in_sizes[1] / CZ;              // total pixels (b*n*n)
    const int T = in_sizes[0] / in_sizes[1];     // number of templates

    const size_t smem = (size_t)(2*P*XST + 2*CZ*HD + 3*P*QST + 3*P*NH) * sizeof(float);
    cudaFuncSetAttribute(tpa_fused, cudaFuncAttributeMaxDynamicSharedMemorySize, (int)smem);

    const int grid = (R + P - 1) / P;
    tpa_fused<<<grid, NT, smem>>>(tmpl, pair, lpg, lpb, ltg, ltb,
                                  Wq, Wk, Wv, Wg, bg, Wo, bo, out, R, T);
}

// round 3
// speedup vs baseline: 1.4835x; 1.4835x over previous
#include <cuda_runtime.h>
#include <cstdint>

#define CZ  128
#define HD  64
#define P   64      // pixels per CTA
#define NT  256
#define XST 132     // stride for 128-wide [row][k] tiles (xs, wt)
#define QST 66      // stride for 64-wide [row][c] tiles (qs, ks)

static __device__ __forceinline__ float tf32r(float x) {
    float y; asm("cvt.rna.tf32.f32 %0, %1;" : "=f"(y) : "f"(x)); return y;
}

static __device__ __forceinline__ void mma8(float* d,
    uint32_t a0, uint32_t a1, uint32_t a2, uint32_t a3, uint32_t b0, uint32_t b1)
{
    asm volatile("mma.sync.aligned.m16n8k8.row.col.f32.tf32.tf32.f32 "
        "{%0,%1,%2,%3}, {%4,%5,%6,%7}, {%8,%9}, {%0,%1,%2,%3};"
        : "+f"(d[0]), "+f"(d[1]), "+f"(d[2]), "+f"(d[3])
        : "r"(a0), "r"(a1), "r"(a2), "r"(a3), "r"(b0), "r"(b1));
}

// Warp computes 16 rows (mt) x 64 cols (nh) with K = 8*KT.
// A: [row][k] stride ast; B: wt[n][k] stride XST (col-major for mma).
static __device__ __forceinline__ void gemm_warp(
    float acc[8][4], const float* A, int ast, const float* wt,
    int mt, int nh, int gid, int tig, int KT)
{
    const float* a0p = A + (mt * 16 + gid) * ast + tig;
    const float* a1p = a0p + 8 * ast;
    const float* bp  = wt + (nh * 64 + gid) * XST + tig;
    #pragma unroll 2
    for (int kt = 0; kt < KT; kt++) {
        const int k0 = kt * 8;
        uint32_t a0 = __float_as_uint(a0p[k0]);
        uint32_t a1 = __float_as_uint(a1p[k0]);
        uint32_t a2 = __float_as_uint(a0p[k0 + 4]);
        uint32_t a3 = __float_as_uint(a1p[k0 + 4]);
        #pragma unroll
        for (int nt = 0; nt < 8; nt++) {
            uint32_t b0 = __float_as_uint(bp[nt * 8 * XST + k0]);
            uint32_t b1 = __float_as_uint(bp[nt * 8 * XST + k0 + 4]);
            mma8(acc[nt], a0, a1, a2, a3, b0, b1);
        }
    }
}

// LayerNorm 64 rows x 128 cols -> tf32 into [row][k] stride XST.
static __device__ __forceinline__ void ln64(
    const float* __restrict__ src, long base, int R, float* dst,
    float4 g4, float4 b4, int wid, int lane)
{
    const int c4 = lane * 4;
    #pragma unroll 1
    for (int r = wid; r < P; r += NT / 32) {
        long row = base + r;
        float4 x = make_float4(0.f, 0.f, 0.f, 0.f);
        if (row < R) x = *(const float4*)(src + row * (long)CZ + c4);
        float s = x.x + x.y + x.z + x.w;
        float q = fmaf(x.x, x.x, fmaf(x.y, x.y, fmaf(x.z, x.z, x.w * x.w)));
        #pragma unroll
        for (int o = 16; o; o >>= 1) {
            s += __shfl_xor_sync(0xffffffffu, s, o);
            q += __shfl_xor_sync(0xffffffffu, q, o);
        }
        float m  = s * (1.f / CZ);
        float v  = fmaxf(q * (1.f / CZ) - m * m, 0.f);
        float ri = rsqrtf(v + 1e-5f);
        float4 y;
        y.x = tf32r((x.x - m) * ri * g4.x + b4.x);
        y.y = tf32r((x.y - m) * ri * g4.y + b4.y);
        y.z = tf32r((x.z - m) * ri * g4.z + b4.z);
        y.w = tf32r((x.w - m) * ri * g4.w + b4.w);
        *(float4*)(dst + r * XST + c4) = y;
    }
}

// Stage two k-major [128][64] weights into wt[n][k] (n = 0..63 from W1, 64..127 from W2).
static __device__ __forceinline__ void stageW2(
    float* wt, const float* __restrict__ W1, const float* __restrict__ W2, int tid)
{
    #pragma unroll 1
    for (int i = tid; i < 4096; i += NT) {
        const int m  = i >> 11;
        const int k  = (i >> 4) & 127;
        const int ng = i & 15;
        const float* Ws = m ? W2 : W1;
        float4 w = *(const float4*)(Ws + k * HD + ng * 4);
        const int n = m * 64 + ng * 4;
        wt[(n + 0) * XST + k] = tf32r(w.x);
        wt[(n + 1) * XST + k] = tf32r(w.y);
        wt[(n + 2) * XST + k] = tf32r(w.z);
        wt[(n + 3) * XST + k] = tf32r(w.w);
    }
}

__global__ void __launch_bounds__(NT, 1)
tpa_mma(const float* __restrict__ tmpl, const float* __restrict__ pair,
        const float* __restrict__ lpg, const float* __restrict__ lpb,
        const float* __restrict__ ltg, const float* __restrict__ ltb,
        const float* __restrict__ Wq,  const float* __restrict__ Wk,
        const float* __restrict__ Wv,  const float* __restrict__ Wg,
        const float* __restrict__ bg,  const float* __restrict__ Wo,
        const float* __restrict__ bo,  float* __restrict__ out,
        int R, int T)
{
    extern __shared__ float smf[];
    float* xs  = smf;                 // 64 x XST : LN'd activations
    float* wt  = xs + P * XST;        // 128 x XST: staged weights [n][k]
    float* qs  = wt + 128 * XST;      // 64 x QST : Q
    float* ks  = qs + P * QST;        // 64 x QST : K_t / vals
    float* rs  = ks + P * QST;        // 256 : rescale / 1/l
    float* ws  = rs + NT;             // 256 : new weight
    float* bgs = ws + NT;             // 64
    float* bos = bgs + HD;            // 128

    const int tid  = threadIdx.x;
    const int lane = tid & 31;
    const int wid  = tid >> 5;
    const int mt   = wid & 3;         // m-tile (16 rows each)
    const int nh   = wid >> 2;        // n half (64 cols each)
    const int gid  = lane >> 2;
    const int tig  = lane & 3;
    const long base = (long)blockIdx.x * P;

    if (tid < HD)  bgs[tid] = bg[tid];
    if (tid < CZ)  bos[tid] = bo[tid];

    const int c4 = lane * 4;
    const float4 gp = *(const float4*)(lpg + c4), bp = *(const float4*)(lpb + c4);
    const float4 gt = *(const float4*)(ltg + c4), bt = *(const float4*)(ltb + c4);

    // ---------------- Phase A: LN(pair), Wq|Wg, QG GEMM ----------------
    ln64(pair, base, R, xs, gp, bp, wid, lane);
    stageW2(wt, Wq, Wg, tid);
    __syncthreads();

    float g[8][4];
    {
        float qga[8][4] = {};
        gemm_warp(qga, xs, XST, wt, mt, nh, gid, tig, 16);
        if (nh == 0) {               // Q -> smem
            const int p0 = mt * 16 + gid, p1 = p0 + 8;
            #pragma unroll
            for (int nt = 0; nt < 8; nt++) {
                const int c = nt * 8 + tig * 2;
                qs[p0 * QST + c]     = qga[nt][0];
                qs[p0 * QST + c + 1] = qga[nt][1];
                qs[p1 * QST + c]     = qga[nt][2];
                qs[p1 * QST + c + 1] = qga[nt][3];
            }
        } else {                     // G kept in fragments (sigmoid)
            #pragma unroll
            for (int nt = 0; nt < 8; nt++) {
                const int c = nt * 8 + tig * 2;
                g[nt][0] = 1.f / (1.f + __expf(-(qga[nt][0] + bgs[c])));
                g[nt][1] = 1.f / (1.f + __expf(-(qga[nt][1] + bgs[c + 1])));
                g[nt][2] = 1.f / (1.f + __expf(-(qga[nt][2] + bgs[c])));
                g[nt][3] = 1.f / (1.f + __expf(-(qga[nt][3] + bgs[c + 1])));
            }
        }
    }
    __syncthreads();

    // ---------------- Phase B: Wk|Wv, template loop ----------------
    stageW2(wt, Wk, Wv, tid);
    ln64(tmpl, base, R, xs, gt, bt, wid, lane);

    float m_run = __int_as_float(0xff800000), l_run = 0.f;
    float vAcc[8][4] = {};
    __syncthreads();

    #pragma unroll 1
    for (int t = 0; t < T; t++) {
        float kv[8][4] = {};
        gemm_warp(kv, xs, XST, wt, mt, nh, gid, tig, 16);
        if (nh == 0) {               // K -> smem
            const int p0 = mt * 16 + gid, p1 = p0 + 8;
            #pragma unroll
            for (int nt = 0; nt < 8; nt++) {
                const int c = nt * 8 + tig * 2;
                ks[p0 * QST + c]     = kv[nt][0];
                ks[p0 * QST + c + 1] = kv[nt][1];
                ks[p1 * QST + c]     = kv[nt][2];
                ks[p1 * QST + c + 1] = kv[nt][3];
            }
        }
        __syncthreads();

        // scalar scores + online softmax: thread owns (p = tid>>2, h = tid&3)
        {
            const int sp = tid >> 2, sh = tid & 3;
            const float* qp = qs + sp * QST + sh * 16;
            const float* kp = ks + sp * QST + sh * 16;
            float sdot = 0.f;
            #pragma unroll
            for (int d = 0; d < 16; d++) sdot = fmaf(qp[d], kp[d], sdot);
            sdot *= 0.25f;           // 1/sqrt(D=16)
            float mn = fmaxf(m_run, sdot);
            float rr = __expf(m_run - mn);
            float ww = __expf(sdot - mn);
            l_run = l_run * rr + ww;
            m_run = mn;
            rs[tid] = rr;
            ws[tid] = ww;
        }
        __syncthreads();

        if (nh == 1) {               // V online accumulate in fragments
            const int p0 = mt * 16 + gid, p1 = p0 + 8;
            #pragma unroll
            for (int nt = 0; nt < 8; nt++) {
                const int h = nt >> 1;
                float rr0 = rs[p0 * 4 + h], ww0 = ws[p0 * 4 + h];
                float rr1 = rs[p1 * 4 + h], ww1 = ws[p1 * 4 + h];
                vAcc[nt][0] = fmaf(vAcc[nt][0], rr0, ww0 * kv[nt][0]);
                vAcc[nt][1] = fmaf(vAcc[nt][1], rr0, ww0 * kv[nt][1]);
                vAcc[nt][2] = fmaf(vAcc[nt][2], rr1, ww1 * kv[nt][2]);
                vAcc[nt][3] = fmaf(vAcc[nt][3], rr1, ww1 * kv[nt][3]);
            }
        }
        if (t + 1 < T)
            ln64(tmpl + (long)(t + 1) * R * CZ, base, R, xs, gt, bt, wid, lane);
        __syncthreads();
    }

    // ---------------- Phase C: finalize, Wo, O GEMM ----------------
    rs[tid] = 1.f / l_run;           // linv per (p,h)
    {   // stage Wo[k=64][n=128] -> wt[n][k]
        #pragma unroll 1
        for (int i = tid; i < 2048; i += NT) {
            const int k = i >> 5, ng = i & 31;
            float4 w = *(const float4*)(Wo + k * CZ + ng * 4);
            const int n = ng * 4;
            wt[(n + 0) * XST + k] = tf32r(w.x);
            wt[(n + 1) * XST + k] = tf32r(w.y);
            wt[(n + 2) * XST + k] = tf32r(w.z);
            wt[(n + 3) * XST + k] = tf32r(w.w);
        }
    }
    __syncthreads();

    if (nh == 1) {                   // vals = vAcc * G * linv -> ks
        const int p0 = mt * 16 + gid, p1 = p0 + 8;
        #pragma unroll
        for (int nt = 0; nt < 8; nt++) {
            const int c = nt * 8 + tig * 2;
            const int h = nt >> 1;
            float li0 = rs[p0 * 4 + h], li1 = rs[p1 * 4 + h];
            ks[p0 * QST + c]     = tf32r(vAcc[nt][0] * g[nt][0] * li0);
            ks[p0 * QST + c + 1] = tf32r(vAcc[nt][1] * g[nt][1] * li0);
            ks[p1 * QST + c]     = tf32r(vAcc[nt][2] * g[nt][2] * li1);
            ks[p1 * QST + c + 1] = tf32r(vAcc[nt][3] * g[nt][3] * li1);
        }
    }
    __syncthreads();

    {
        float oc[8][4] = {};
        gemm_warp(oc, ks, QST, wt, mt, nh, gid, tig, 8);
        const long r0 = base + mt * 16 + gid, r1 = r0 + 8;
        #pragma unroll
        for (int nt = 0; nt < 8; nt++) {
            const int c = nh * 64 + nt * 8 + tig * 2;
            if (r0 < R) {
                float2 v = make_float2(oc[nt][0] + bos[c], oc[nt][1] + bos[c + 1]);
                *(float2*)(out + r0 * (long)CZ + c) = v;
            }
            if (r1 < R) {
                float2 v = make_float2(oc[nt][2] + bos[c], oc[nt][3] + bos[c + 1]);
                *(float2*)(out + r1 * (long)CZ + c) = v;
            }
        }
    }
}

extern "C" void kernel_launch(void* const* d_in, const int* in_sizes, int n_in,
                              void* d_out, int out_size)
{
    const float* tmpl = (const float*)d_in[0];
    const float* pair = (const float*)d_in[1];
    const float* lpg  = (const float*)d_in[2];
    const float* lpb  = (const float*)d_in[3];
    const float* ltg  = (const float*)d_in[4];
    const float* ltb  = (const float*)d_in[5];
    const float* Wq   = (const float*)d_in[6];
    const float* Wk   = (const float*)d_in[7];
    const float* Wv   = (const float*)d_in[8];
    const float* Wg   = (const float*)d_in[9];
    const float* bg   = (const float*)d_in[10];
    const float* Wo   = (const float*)d_in[11];
    const float* bo   = (const float*)d_in[12];
    float* out = (float*)d_out;

    const int R = in_sizes[1] / CZ;           // b*n*n pixels
    const int T = in_sizes[0] / in_sizes[1];  // templates

    const size_t smem = (size_t)(P * XST + 128 * XST + 2 * P * QST + 2 * NT + HD + CZ) * sizeof(float);
    cudaFuncSetAttribute(tpa_mma, cudaFuncAttributeMaxDynamicSharedMemorySize, (int)smem);

    const int grid = (R + P - 1) / P;
    tpa_mma<<<grid, NT, smem>>>(tmpl, pair, lpg, lpb, ltg, ltb,
                                Wq, Wk, Wv, Wg, bg, Wo, bo, out, R, T);
}

// round 4
// speedup vs baseline: 2.5876x; 1.7443x over previous
#include <cuda_runtime.h>
#include <cstdint>

#define CZ  128
#define HD  64
#define P   64      // pixels per CTA
#define NT  512
#define NW  16      // warps
#define XST 132     // stride for 128-wide [row][k] tiles
#define QST 66      // stride for 64-wide [row][c] tiles

static __device__ __forceinline__ float tf32r(float x) {
    float y; asm("cvt.rna.tf32.f32 %0, %1;" : "=f"(y) : "f"(x)); return y;
}

static __device__ __forceinline__ void mma8(float* d,
    uint32_t a0, uint32_t a1, uint32_t a2, uint32_t a3, uint32_t b0, uint32_t b1)
{
    asm volatile("mma.sync.aligned.m16n8k8.row.col.f32.tf32.tf32.f32 "
        "{%0,%1,%2,%3}, {%4,%5,%6,%7}, {%8,%9}, {%0,%1,%2,%3};"
        : "+f"(d[0]), "+f"(d[1]), "+f"(d[2]), "+f"(d[3])
        : "r"(a0), "r"(a1), "r"(a2), "r"(a3), "r"(b0), "r"(b1));
}

// Warp computes 16 rows (mt) x 32 cols (nq) with K = 8*KT.
// A: [row][k] stride ast; B: wt[n][k] stride XST (col-major for mma).
static __device__ __forceinline__ void gemm_warp(
    float acc[4][4], const float* A, int ast, const float* wt,
    int mt, int nq, int gid, int tig, int KT)
{
    const float* a0p = A + (mt * 16 + gid) * ast + tig;
    const float* a1p = a0p + 8 * ast;
    const float* bp  = wt + (nq * 32 + gid) * XST + tig;
    #pragma unroll 4
    for (int kt = 0; kt < KT; kt++) {
        const int k0 = kt * 8;
        uint32_t a0 = __float_as_uint(a0p[k0]);
        uint32_t a1 = __float_as_uint(a1p[k0]);
        uint32_t a2 = __float_as_uint(a0p[k0 + 4]);
        uint32_t a3 = __float_as_uint(a1p[k0 + 4]);
        #pragma unroll
        for (int nt = 0; nt < 4; nt++) {
            uint32_t b0 = __float_as_uint(bp[nt * 8 * XST + k0]);
            uint32_t b1 = __float_as_uint(bp[nt * 8 * XST + k0 + 4]);
            mma8(acc[nt], a0, a1, a2, a3, b0, b1);
        }
    }
}

// LayerNorm 64 rows x 128 cols -> tf32 into [row][k] stride XST.
static __device__ __forceinline__ void ln64(
    const float* __restrict__ src, long base, int R, float* dst,
    float4 g4, float4 b4, int wid, int lane)
{
    const int c4 = lane * 4;
    #pragma unroll
    for (int r = wid; r < P; r += NW) {
        long row = base + r;
        float4 x = make_float4(0.f, 0.f, 0.f, 0.f);
        if (row < R) x = *(const float4*)(src + row * (long)CZ + c4);
        float s = x.x + x.y + x.z + x.w;
        float q = fmaf(x.x, x.x, fmaf(x.y, x.y, fmaf(x.z, x.z, x.w * x.w)));
        #pragma unroll
        for (int o = 16; o; o >>= 1) {
            s += __shfl_xor_sync(0xffffffffu, s, o);
            q += __shfl_xor_sync(0xffffffffu, q, o);
        }
        float m  = s * (1.f / CZ);
        float v  = fmaxf(q * (1.f / CZ) - m * m, 0.f);
        float ri = rsqrtf(v + 1e-5f);
        float4 y;
        y.x = tf32r((x.x - m) * ri * g4.x + b4.x);
        y.y = tf32r((x.y - m) * ri * g4.y + b4.y);
        y.z = tf32r((x.z - m) * ri * g4.z + b4.z);
        y.w = tf32r((x.w - m) * ri * g4.w + b4.w);
        *(float4*)(dst + r * XST + c4) = y;
    }
}

// Stage two k-major [128][64] weights into wt[n][k] (n = 0..63 W1, 64..127 W2).
static __device__ __forceinline__ void stageW2(
    float* wt, const float* __restrict__ W1, const float* __restrict__ W2, int tid)
{
    #pragma unroll 1
    for (int i = tid; i < 4096; i += NT) {
        const int m  = i >> 11;
        const int k  = (i >> 4) & 127;
        const int ng = i & 15;
        const float* Ws = m ? W2 : W1;
        float4 w = *(const float4*)(Ws + k * HD + ng * 4);
        const int n = m * 64 + ng * 4;
        wt[(n + 0) * XST + k] = tf32r(w.x);
        wt[(n + 1) * XST + k] = tf32r(w.y);
        wt[(n + 2) * XST + k] = tf32r(w.z);
        wt[(n + 3) * XST + k] = tf32r(w.w);
    }
}

__global__ void __launch_bounds__(NT, 1)
tpa_mma2(const float* __restrict__ tmpl, const float* __restrict__ pair,
         const float* __restrict__ lpg, const float* __restrict__ lpb,
         const float* __restrict__ ltg, const float* __restrict__ ltb,
         const float* __restrict__ Wq,  const float* __restrict__ Wk,
         const float* __restrict__ Wv,  const float* __restrict__ Wg,
         const float* __restrict__ bg,  const float* __restrict__ Wo,
         const float* __restrict__ bo,  float* __restrict__ out,
         int R, int T)
{
    extern __shared__ float smf[];
    float* xs0 = smf;                 // 64 x XST : LN buffer A
    float* xs1 = xs0 + P * XST;       // 64 x XST : LN buffer B
    float* wt  = xs1 + P * XST;       // 128 x XST: staged weights [n][k]
    float* qs  = wt + 128 * XST;      // 64 x QST : Q
    float* ks  = qs + P * QST;        // 64 x QST : K_t / vals
    float* rs  = ks + P * QST;        // 256 : rescale / 1/l
    float* ws  = rs + 256;            // 256 : new weight
    float* bgs = ws + 256;            // 64
    float* bos = bgs + HD;            // 128

    const int tid  = threadIdx.x;
    const int lane = tid & 31;
    const int wid  = tid >> 5;
    const int mt   = wid & 3;         // m-tile (16 rows)
    const int nq   = wid >> 2;        // n quarter (32 cols)
    const int gid  = lane >> 2;
    const int tig  = lane & 3;
    const long base = (long)blockIdx.x * P;

    if (tid < HD)  bgs[tid] = bg[tid];
    else if (tid >= 64 && tid < 64 + CZ) bos[tid - 64] = bo[tid - 64];

    const int c4 = lane * 4;
    const float4 gp = *(const float4*)(lpg + c4), bp = *(const float4*)(lpb + c4);
    const float4 gt = *(const float4*)(ltg + c4), bt = *(const float4*)(ltb + c4);

    // ---------------- Phase A: LN(pair)->xs0, Wq|Wg, QG GEMM ----------------
    ln64(pair, base, R, xs0, gp, bp, wid, lane);
    stageW2(wt, Wq, Wg, tid);
    __syncthreads();

    float g[4][4];                    // only meaningful on nq>=2 warps
    {
        float qga[4][4] = {};
        gemm_warp(qga, xs0, XST, wt, mt, nq, gid, tig, 16);
        if (nq < 2) {                 // Q -> smem
            const int p0 = mt * 16 + gid, p1 = p0 + 8;
            #pragma unroll
            for (int nt = 0; nt < 4; nt++) {
                const int c = nq * 32 + nt * 8 + tig * 2;
                qs[p0 * QST + c]     = qga[nt][0];
                qs[p0 * QST + c + 1] = qga[nt][1];
                qs[p1 * QST + c]     = qga[nt][2];
                qs[p1 * QST + c + 1] = qga[nt][3];
            }
        } else {                      // G kept in fragments (sigmoid)
            #pragma unroll
            for (int nt = 0; nt < 4; nt++) {
                const int c = (nq - 2) * 32 + nt * 8 + tig * 2;
                g[nt][0] = 1.f / (1.f + __expf(-(qga[nt][0] + bgs[c])));
                g[nt][1] = 1.f / (1.f + __expf(-(qga[nt][1] + bgs[c + 1])));
                g[nt][2] = 1.f / (1.f + __expf(-(qga[nt][2] + bgs[c])));
                g[nt][3] = 1.f / (1.f + __expf(-(qga[nt][3] + bgs[c + 1])));
            }
        }
    }
    // LN(t=0) -> xs1 (QG GEMM read xs0; no conflict)
    ln64(tmpl, base, R, xs1, gt, bt, wid, lane);
    __syncthreads();

    // Q into registers of score threads (wids 0..7 <-> tid<256), Wk|Wv staged
    float qreg[16];
    float m_run = __int_as_float(0xff800000), l_run = 0.f;
    if (tid < 256) {
        const int sp = tid >> 2, sh = tid & 3;
        const float* qp = qs + sp * QST + sh * 16;
        #pragma unroll
        for (int d = 0; d < 16; d++) qreg[d] = qp[d];
    }
    stageW2(wt, Wk, Wv, tid);
    float vAcc[4][4] = {};
    __syncthreads();

    // ---------------- template loop (2 syncs per t) ----------------
    #pragma unroll 1
    for (int t = 0; t < T; t++) {
        float* xsc = (t & 1) ? xs0 : xs1;     // buf(t) = (t+1)&1 pattern: t0->xs1
        float kv[4][4] = {};
        gemm_warp(kv, xsc, XST, wt, mt, nq, gid, tig, 16);
        if (nq < 2) {                 // K -> smem
            const int p0 = mt * 16 + gid, p1 = p0 + 8;
            #pragma unroll
            for (int nt = 0; nt < 4; nt++) {
                const int c = nq * 32 + nt * 8 + tig * 2;
                ks[p0 * QST + c]     = kv[nt][0];
                ks[p0 * QST + c + 1] = kv[nt][1];
                ks[p1 * QST + c]     = kv[nt][2];
                ks[p1 * QST + c + 1] = kv[nt][3];
            }
        }
        __syncthreads();

        // scores + online softmax (tid<256 owns (p,h)); LN(t+1) runs concurrently
        if (tid < 256) {
            const int sp = tid >> 2, sh = tid & 3;
            const float* kp = ks + sp * QST + sh * 16;
            float sdot = 0.f;
            #pragma unroll
            for (int d = 0; d < 16; d++) sdot = fmaf(qreg[d], kp[d], sdot);
            sdot *= 0.25f;            // 1/sqrt(D=16)
            float mn = fmaxf(m_run, sdot);
            float rr = __expf(m_run - mn);
            float ww = __expf(sdot - mn);
            l_run = l_run * rr + ww;
            m_run = mn;
            rs[tid] = rr;
            ws[tid] = ww;
        }
        if (t + 1 < T)
            ln64(tmpl + (long)(t + 1) * R * CZ, base, R,
                 (t & 1) ? xs1 : xs0, gt, bt, wid, lane);
        __syncthreads();

        if (nq >= 2) {                // V online accumulate in fragments
            const int p0 = mt * 16 + gid, p1 = p0 + 8;
            const int hb = (nq - 2) * 2;
            #pragma unroll
            for (int nt = 0; nt < 4; nt++) {
                const int h = hb + (nt >> 1);
                float rr0 = rs[p0 * 4 + h], ww0 = ws[p0 * 4 + h];
                float rr1 = rs[p1 * 4 + h], ww1 = ws[p1 * 4 + h];
                vAcc[nt][0] = fmaf(vAcc[nt][0], rr0, ww0 * kv[nt][0]);
                vAcc[nt][1] = fmaf(vAcc[nt][1], rr0, ww0 * kv[nt][1]);
                vAcc[nt][2] = fmaf(vAcc[nt][2], rr1, ww1 * kv[nt][2]);
                vAcc[nt][3] = fmaf(vAcc[nt][3], rr1, ww1 * kv[nt][3]);
            }
        }
        // next GEMM reads other xs buffer; K-write of t+1 vs score-read of t is
        // ordered by the sync at the top of the next iteration's score phase
        __syncthreads();
    }

    // ---------------- Phase C: finalize, Wo, O GEMM ----------------
    if (tid < 256) rs[tid] = 1.f / l_run;     // linv per (p,h)
    {   // stage Wo[k=64][n=128] -> wt[n][k]
        #pragma unroll 1
        for (int i = tid; i < 2048; i += NT) {
            const int k = i >> 5, ng = i & 31;
            float4 w = *(const float4*)(Wo + k * CZ + ng * 4);
            const int n = ng * 4;
            wt[(n + 0) * XST + k] = tf32r(w.x);
            wt[(n + 1) * XST + k] = tf32r(w.y);
            wt[(n + 2) * XST + k] = tf32r(w.z);
            wt[(n + 3) * XST + k] = tf32r(w.w);
        }
    }
    __syncthreads();

    if (nq >= 2) {                    // vals = vAcc * G * linv -> ks
        const int p0 = mt * 16 + gid, p1 = p0 + 8;
        const int hb = (nq - 2) * 2;
        #pragma unroll
        for (int nt = 0; nt < 4; nt++) {
            const int c = (nq - 2) * 32 + nt * 8 + tig * 2;
            const int h = hb + (nt >> 1);
            float li0 = rs[p0 * 4 + h], li1 = rs[p1 * 4 + h];
            ks[p0 * QST + c]     = tf32r(vAcc[nt][0] * g[nt][0] * li0);
            ks[p0 * QST + c + 1] = tf32r(vAcc[nt][1] * g[nt][1] * li0);
            ks[p1 * QST + c]     = tf32r(vAcc[nt][2] * g[nt][2] * li1);
            ks[p1 * QST + c + 1] = tf32r(vAcc[nt][3] * g[nt][3] * li1);
        }
    }
    __syncthreads();

    {
        float oc[4][4] = {};
        gemm_warp(oc, ks, QST, wt, mt, nq, gid, tig, 8);
        const long r0 = base + mt * 16 + gid, r1 = r0 + 8;
        #pragma unroll
        for (int nt = 0; nt < 4; nt++) {
            const int c = nq * 32 + nt * 8 + tig * 2;
            if (r0 < R) {
                float2 v = make_float2(oc[nt][0] + bos[c], oc[nt][1] + bos[c + 1]);
                *(float2*)(out + r0 * (long)CZ + c) = v;
            }
            if (r1 < R) {
                float2 v = make_float2(oc[nt][2] + bos[c], oc[nt][3] + bos[c + 1]);
                *(float2*)(out + r1 * (long)CZ + c) = v;
            }
        }
    }
}

extern "C" void kernel_launch(void* const* d_in, const int* in_sizes, int n_in,
                              void* d_out, int out_size)
{
    const float* tmpl = (const float*)d_in[0];
    const float* pair = (const float*)d_in[1];
    const float* lpg  = (const float*)d_in[2];
    const float* lpb  = (const float*)d_in[3];
    const float* ltg  = (const float*)d_in[4];
    const float* ltb  = (const float*)d_in[5];
    const float* Wq   = (const float*)d_in[6];
    const float* Wk   = (const float*)d_in[7];
    const float* Wv   = (const float*)d_in[8];
    const float* Wg   = (const float*)d_in[9];
    const float* bg   = (const float*)d_in[10];
    const float* Wo   = (const float*)d_in[11];
    const float* bo   = (const float*)d_in[12];
    float* out = (float*)d_out;

    const int R = in_sizes[1] / CZ;           // b*n*n pixels
    const int T = in_sizes[0] / in_sizes[1];  // templates

    const size_t smem = (size_t)(2 * P * XST + 128 * XST + 2 * P * QST
                                 + 2 * 256 + HD + CZ) * sizeof(float);
    cudaFuncSetAttribute(tpa_mma2, cudaFuncAttributeMaxDynamicSharedMemorySize, (int)smem);

    const int grid = (R + P - 1) / P;
    tpa_mma2<<<grid, NT, smem>>>(tmpl, pair, lpg, lpb, ltg, ltb,
                                 Wq, Wk, Wv, Wg, bg, Wo, bo, out, R, T);
}